// round 4
// baseline (speedup 1.0000x reference)
#include <cuda_runtime.h>
#include <math.h>
#include <stdint.h>

#define TT 128
#define NN 1000
#define EE 16000
#define FF 397
#define HH 128
#define DD 8
#define G4 512   // 4*HH
#define BM 128
#define BK 16

// ---- static scratch (allocation-free rule: __device__ globals) ----
__device__ float g_Y [TT*NN*HH];
__device__ float g_H1[TT*NN*HH];
__device__ int   g_cnt  [TT*NN];
__device__ int   g_start[TT*NN];
__device__ int   g_eidx [TT*EE];
__device__ float g_pool [TT*HH];
__device__ float g_Gx   [TT*G4];

// ---- packed f32x2 helpers (sm_103a: 2 fp32 FMAs per FMA-pipe issue) ----
__device__ __forceinline__ void ffma2(unsigned long long& d,
                                      unsigned long long a, unsigned long long b) {
    asm("fma.rn.f32x2 %0, %1, %2, %3;" : "=l"(d) : "l"(a), "l"(b), "l"(d));
}
__device__ __forceinline__ float2 unpack2(unsigned long long v) {
    float2 r;
    asm("mov.b64 {%0, %1}, %2;" : "=f"(r.x), "=f"(r.y) : "l"(v));
    return r;
}

// ---------------- fused CSR build: one block per timestep ----------------
__global__ void __launch_bounds__(1024) csr_kernel(const int* __restrict__ ei) {
    __shared__ int scnt[1024];
    __shared__ int sscan[1024];
    int t = blockIdx.x, tid = threadIdx.x;
    scnt[tid] = 0;
    __syncthreads();
    const int* srcp = ei + t*2*EE;
    const int* dstp = srcp + EE;
    for (int e = tid; e < EE; e += 1024) atomicAdd(&scnt[dstp[e]], 1);
    __syncthreads();
    int v = scnt[tid];
    sscan[tid] = v;
    __syncthreads();
    for (int off = 1; off < 1024; off <<= 1) {
        int u = (tid >= off) ? sscan[tid - off] : 0;
        __syncthreads();
        sscan[tid] += u;
        __syncthreads();
    }
    int start = sscan[tid] - v;
    if (tid < NN) { g_start[t*NN + tid] = start; g_cnt[t*NN + tid] = v; }
    __syncthreads();
    scnt[tid] = start;          // reuse as cursor
    __syncthreads();
    int* eix = g_eidx + t*EE;
    for (int e = tid; e < EE; e += 1024) {
        int d = dstp[e], s = srcp[e];
        int pos = atomicAdd(&scnt[d], 1);
        eix[pos] = s;
    }
}

// ------- GEMM: C[M x 128] = A[M x K] @ W^T + bias, FFMA2 mainloop --------
// BM=128, BN=128, BK=16, 256 threads. Per-thread 8m x 8n, accs packed as
// m-pairs (u64). a-pairs load straight from As (no packs); b is stored
// DUPLICATED in smem so a u64 load gives (b_n, b_n). ~110 regs.
__global__ void __launch_bounds__(256, 2) gemm_bias_kernel(
    const float* __restrict__ A, const float* __restrict__ W,
    const float* __restrict__ bias, float* __restrict__ C, int K)
{
    __shared__ float As [BK][BM];      // 8 KB
    __shared__ float Bs2[BK][2*HH];    // 16 KB, each value duplicated
    int tid = threadIdx.x;
    long m0 = (long)blockIdx.x * BM;

    int tx = tid & 15, ty = tid >> 4;  // n-group, m-group
    int tn = tx * 8, tm = ty * 8;

    unsigned long long acc[4][8];      // [m-pair][n]
    #pragma unroll
    for (int i = 0; i < 4; i++)
        #pragma unroll
        for (int j = 0; j < 8; j++) acc[i][j] = 0ULL;

    int ar = tid >> 1, ak = (tid & 1) * 8;
    const float* Arow = A + (m0 + ar) * (long)K;
    int wc = tid >> 1, wk = (tid & 1) * 8;
    const float* Wrow = W + (long)wc * K;

    for (int k0 = 0; k0 < K; k0 += BK) {
        #pragma unroll
        for (int i = 0; i < 8; i++) {
            int k = k0 + ak + i;
            As[ak + i][ar] = (k < K) ? Arow[k] : 0.f;
        }
        #pragma unroll
        for (int i = 0; i < 8; i++) {
            int k = k0 + wk + i;
            float v = (k < K) ? Wrow[k] : 0.f;
            Bs2[wk + i][2*wc]     = v;
            Bs2[wk + i][2*wc + 1] = v;
        }
        __syncthreads();
        #pragma unroll
        for (int k = 0; k < BK; k++) {
            unsigned long long a[4], b[8];
            const unsigned long long* ap = (const unsigned long long*)&As[k][tm];
            a[0] = ap[0]; a[1] = ap[1]; a[2] = ap[2]; a[3] = ap[3];
            const unsigned long long* bp = (const unsigned long long*)&Bs2[k][2*tn];
            #pragma unroll
            for (int j = 0; j < 8; j++) b[j] = bp[j];
            #pragma unroll
            for (int i = 0; i < 4; i++)
                #pragma unroll
                for (int j = 0; j < 8; j++)
                    ffma2(acc[i][j], a[i], b[j]);
        }
        __syncthreads();
    }

    float bb[8];
    *(float4*)&bb[0] = *(const float4*)&bias[tn];
    *(float4*)&bb[4] = *(const float4*)&bias[tn + 4];
    #pragma unroll
    for (int i = 0; i < 4; i++) {
        float o0[8], o1[8];
        #pragma unroll
        for (int j = 0; j < 8; j++) {
            float2 v = unpack2(acc[i][j]);
            o0[j] = v.x + bb[j];
            o1[j] = v.y + bb[j];
        }
        float* c0 = C + (m0 + tm + 2*i)     * (long)HH + tn;
        float* c1 = C + (m0 + tm + 2*i + 1) * (long)HH + tn;
        *(float4*)&c0[0] = *(float4*)&o0[0];
        *(float4*)&c0[4] = *(float4*)&o0[4];
        *(float4*)&c1[0] = *(float4*)&o1[0];
        *(float4*)&c1[4] = *(float4*)&o1[4];
    }
}

// -------- gather + relu (GIN self-term + neighbor sum + ReLU) --------
__global__ void __launch_bounds__(256) gather_relu_kernel(
    const float* __restrict__ Y, float* __restrict__ Out)
{
    int wid  = threadIdx.x >> 5, lane = threadIdx.x & 31;
    int dst  = blockIdx.x * 8 + wid;
    int t    = blockIdx.y;
    if (dst >= NN) return;
    const float* base = Y + t * NN * HH;
    float4 acc = *(const float4*)&base[dst * HH + lane * 4];
    int s   = g_start[t*NN + dst];
    int cnt = g_cnt  [t*NN + dst];
    const int* ep = g_eidx + t*EE + s;
    int i = 0;
    for (; i + 4 <= cnt; i += 4) {
        int s0 = ep[i], s1 = ep[i+1], s2 = ep[i+2], s3 = ep[i+3];
        float4 v0 = *(const float4*)&base[s0*HH + lane*4];
        float4 v1 = *(const float4*)&base[s1*HH + lane*4];
        float4 v2 = *(const float4*)&base[s2*HH + lane*4];
        float4 v3 = *(const float4*)&base[s3*HH + lane*4];
        acc.x += v0.x + v1.x + v2.x + v3.x;
        acc.y += v0.y + v1.y + v2.y + v3.y;
        acc.z += v0.z + v1.z + v2.z + v3.z;
        acc.w += v0.w + v1.w + v2.w + v3.w;
    }
    for (; i < cnt; i++) {
        int s0 = ep[i];
        float4 v = *(const float4*)&base[s0*HH + lane*4];
        acc.x += v.x; acc.y += v.y; acc.z += v.z; acc.w += v.w;
    }
    acc.x = fmaxf(acc.x, 0.f); acc.y = fmaxf(acc.y, 0.f);
    acc.z = fmaxf(acc.z, 0.f); acc.w = fmaxf(acc.w, 0.f);
    *(float4*)&Out[(t*NN + dst)*HH + lane*4] = acc;
}

// ---------------- mean pool over N ----------------
__global__ void pool_kernel(const float* __restrict__ Hin) {
    int t = blockIdx.x, c = threadIdx.x;   // 128 threads
    const float* p = Hin + t*NN*HH + c;
    float s0 = 0, s1 = 0, s2 = 0, s3 = 0;
    for (int n = 0; n < NN; n += 4) {
        s0 += p[(n+0)*HH];
        s1 += p[(n+1)*HH];
        s2 += p[(n+2)*HH];
        s3 += p[(n+3)*HH];
    }
    g_pool[t*HH + c] = (s0 + s1 + s2 + s3) * (1.f / NN);
}

// -------- input-side LSTM gates --------
__global__ void __launch_bounds__(512) gx_kernel(
    const int* __restrict__ dok, const float* __restrict__ emb,
    const float* __restrict__ w_ih, const float* __restrict__ b_ih,
    const float* __restrict__ b_hh)
{
    __shared__ float sseq[HH + DD];
    int t = blockIdx.x, j = threadIdx.x;
    if (j < HH)            sseq[j] = g_pool[t*HH + j];
    else if (j < HH + DD)  sseq[j] = emb[dok[t]*DD + (j - HH)];
    __syncthreads();
    const float* wr = w_ih + j * (HH + DD);
    float a0 = b_ih[j] + b_hh[j], a1 = 0.f;
    #pragma unroll
    for (int k = 0; k < HH + DD; k += 2) {
        a0 += wr[k]   * sseq[k];
        a1 += wr[k+1] * sseq[k+1];
    }
    g_Gx[t*G4 + j] = a0 + a1;
}

// ---------------- sequential LSTM + final FC ----------------
#define SPITCH 68
__global__ void __launch_bounds__(512) lstm_kernel(
    const float* __restrict__ w_hh, const float* __restrict__ w_fc,
    const float* __restrict__ b_fc, float* __restrict__ out)
{
    extern __shared__ float sm[];
    float* sW   = sm;                  // 512*68
    float* sh   = sW + G4*SPITCH;      // 128
    float* sg   = sh + HH;             // 512
    float* sred = sg + G4;             // 32

    int tid = threadIdx.x;

    float4 rw[16];
    const float4* wg4 = (const float4*)(w_hh + tid * HH);
    #pragma unroll
    for (int i = 0; i < 16; i++) rw[i] = wg4[i];          // cols 0..63

    for (int i = tid; i < G4 * 64; i += 512) {            // cols 64..127
        int r = i >> 6, c = i & 63;
        sW[r*SPITCH + c] = w_hh[r*HH + 64 + c];
    }
    if (tid < HH) sh[tid] = 0.f;
    float c_state = 0.f;
    float wfc = (tid < HH) ? w_fc[tid] : 0.f;
    float bfc = b_fc[0];
    __syncthreads();

    const float4* wr4 = (const float4*)(sW + tid * SPITCH);

    for (int t = 0; t < TT; t++) {
        const float4* sh4 = (const float4*)sh;
        float a0 = 0, a1 = 0, a2 = 0, a3 = 0;
        #pragma unroll
        for (int k = 0; k < 16; k++) {
            float4 hv = sh4[k]; float4 w = rw[k];
            a0 += w.x*hv.x; a1 += w.y*hv.y; a2 += w.z*hv.z; a3 += w.w*hv.w;
        }
        #pragma unroll
        for (int k = 0; k < 16; k++) {
            float4 hv = sh4[16 + k]; float4 w = wr4[k];
            a0 += w.x*hv.x; a1 += w.y*hv.y; a2 += w.z*hv.z; a3 += w.w*hv.w;
        }
        sg[tid] = g_Gx[t*G4 + tid] + (a0 + a1) + (a2 + a3);
        __syncthreads();
        if (tid < HH) {
            float ig = 1.f / (1.f + expf(-sg[tid]));
            float fg = 1.f / (1.f + expf(-sg[tid + HH]));
            float gg = tanhf(sg[tid + 2*HH]);
            float og = 1.f / (1.f + expf(-sg[tid + 3*HH]));
            c_state = fg * c_state + ig * gg;
            float h = og * tanhf(c_state);
            sh[tid] = h;
            float p = h * wfc;
            #pragma unroll
            for (int o = 16; o > 0; o >>= 1) p += __shfl_down_sync(0xffffffffu, p, o);
            if ((tid & 31) == 0) sred[tid >> 5] = p;
        }
        __syncthreads();
        if (tid == 0) out[t] = sred[0] + sred[1] + sred[2] + sred[3] + bfc;
    }
}

// ---------------- launch ----------------
extern "C" void kernel_launch(void* const* d_in, const int* in_sizes, int n_in,
                              void* d_out, int out_size)
{
    const float* x    = (const float*)d_in[0];
    const int*   ei   = (const int*)  d_in[1];
    const int*   dok  = (const int*)  d_in[2];
    const float* w1   = (const float*)d_in[3];
    const float* b1   = (const float*)d_in[4];
    const float* w2   = (const float*)d_in[5];
    const float* b2   = (const float*)d_in[6];
    const float* emb  = (const float*)d_in[7];
    const float* w_ih = (const float*)d_in[8];
    const float* w_hh = (const float*)d_in[9];
    const float* b_ih = (const float*)d_in[10];
    const float* b_hh = (const float*)d_in[11];
    const float* w_fc = (const float*)d_in[12];
    const float* b_fc = (const float*)d_in[13];
    float* out = (float*)d_out;

    float *pY, *pH1;
    cudaGetSymbolAddress((void**)&pY,  g_Y);
    cudaGetSymbolAddress((void**)&pH1, g_H1);

    // fused CSR build (shared by both GIN layers)
    csr_kernel<<<TT, 1024>>>(ei);

    // GIN layer 1: y = x@w1^T + b1 ; h1 = relu(y[dst] + sum y[src])
    gemm_bias_kernel<<<TT*NN/BM, 256>>>(x, w1, b1, pY, FF);
    dim3 gg((NN + 7)/8, TT);
    gather_relu_kernel<<<gg, 256>>>(pY, pH1);

    // GIN layer 2
    gemm_bias_kernel<<<TT*NN/BM, 256>>>(pH1, w2, b2, pY, HH);
    gather_relu_kernel<<<gg, 256>>>(pY, pH1);

    // pool, LSTM input gates, sequential LSTM + FC
    pool_kernel<<<TT, HH>>>(pH1);
    gx_kernel<<<TT, 512>>>(dok, emb, w_ih, b_ih, b_hh);

    size_t lsm = (size_t)(G4*SPITCH + HH + G4 + 32) * sizeof(float);
    cudaFuncSetAttribute(lstm_kernel, cudaFuncAttributeMaxDynamicSharedMemorySize, (int)lsm);
    lstm_kernel<<<1, 512, lsm>>>(w_hh, w_fc, b_fc, out);
}

// round 5
// speedup vs baseline: 1.8658x; 1.8658x over previous
#include <cuda_runtime.h>
#include <math.h>
#include <stdint.h>

#define TT 128
#define NN 1000
#define EE 16000
#define FF 397
#define HH 128
#define DD 8
#define G4 512   // 4*HH
#define BM 128
#define BK 16

// ---- static scratch (allocation-free rule: __device__ globals) ----
__device__ float g_Y [TT*NN*HH];
__device__ float g_H1[TT*NN*HH];
__device__ int   g_cnt  [TT*NN];
__device__ int   g_start[TT*NN];
__device__ int   g_eidx [TT*EE];
__device__ float g_pool [TT*HH];
__device__ float g_Gx   [TT*G4];

// ---- packed f32x2 helpers ----
__device__ __forceinline__ unsigned long long pack2(float x, float y) {
    unsigned long long r;
    asm("mov.b64 %0, {%1, %2};" : "=l"(r) : "f"(x), "f"(y));
    return r;
}
__device__ __forceinline__ void ffma2(unsigned long long& d,
                                      unsigned long long a, unsigned long long b) {
    asm("fma.rn.f32x2 %0, %1, %2, %3;" : "=l"(d) : "l"(a), "l"(b), "l"(d));
}
__device__ __forceinline__ float2 unpack2(unsigned long long v) {
    float2 r;
    asm("mov.b64 {%0, %1}, %2;" : "=f"(r.x), "=f"(r.y) : "l"(v));
    return r;
}

// ---------------- fused CSR build: one block per timestep ----------------
__global__ void __launch_bounds__(1024) csr_kernel(const int* __restrict__ ei) {
    __shared__ int scnt[1024];
    __shared__ int sscan[1024];
    int t = blockIdx.x, tid = threadIdx.x;
    scnt[tid] = 0;
    __syncthreads();
    const int* srcp = ei + t*2*EE;
    const int* dstp = srcp + EE;
    for (int e = tid; e < EE; e += 1024) atomicAdd(&scnt[dstp[e]], 1);
    __syncthreads();
    int v = scnt[tid];
    sscan[tid] = v;
    __syncthreads();
    for (int off = 1; off < 1024; off <<= 1) {
        int u = (tid >= off) ? sscan[tid - off] : 0;
        __syncthreads();
        sscan[tid] += u;
        __syncthreads();
    }
    int start = sscan[tid] - v;
    if (tid < NN) { g_start[t*NN + tid] = start; g_cnt[t*NN + tid] = v; }
    __syncthreads();
    scnt[tid] = start;          // reuse as cursor
    __syncthreads();
    int* eix = g_eidx + t*EE;
    for (int e = tid; e < EE; e += 1024) {
        int d = dstp[e], s = srcp[e];
        int pos = atomicAdd(&scnt[d], 1);
        eix[pos] = s;
    }
}

// ------- GEMM: C[M x 128] = A[M x K] @ W^T + bias, FFMA2 mainloop --------
// BM=128, BN=128, BK=16, 256 threads, 2 CTAs/SM. Per-thread 8m x 8n.
// B smem layout: u64 slot j of row k = (W[j][k], W[j+64][k]) -> thread tx
// reads slots {tx, tx+16, tx+32, tx+48}: 8B lane stride, conflict-free.
// a-operands broadcast-LDS.128, duplicated into f32x2 via mov (ALU pipe).
__global__ void __launch_bounds__(256, 2) gemm_bias_kernel(
    const float* __restrict__ A, const float* __restrict__ W,
    const float* __restrict__ bias, float* __restrict__ C, int K)
{
    __shared__ float As [BK][BM];      // 8 KB
    __shared__ float Bsf[BK][2*64];    // 8 KB, u64-slot pair layout
    int tid = threadIdx.x;
    long m0 = (long)blockIdx.x * BM;

    int tx = tid & 15, ty = tid >> 4;  // n-group, m-group
    int tm = ty * 8;

    unsigned long long acc[8][4];      // [m][n-slot r] ; slot r = cols (tx+16r, tx+16r+64)
    #pragma unroll
    for (int i = 0; i < 8; i++)
        #pragma unroll
        for (int j = 0; j < 4; j++) acc[i][j] = 0ULL;

    int ar = tid >> 1, ak = (tid & 1) * 8;
    const float* Arow = A + (m0 + ar) * (long)K;
    int wn = tid >> 1, wk = (tid & 1) * 8;
    const float* Wrow = W + (long)wn * K;
    int wslot = 2*(wn & 63) + (wn >> 6);

    for (int k0 = 0; k0 < K; k0 += BK) {
        #pragma unroll
        for (int i = 0; i < 8; i++) {
            int k = k0 + ak + i;
            As[ak + i][ar] = (k < K) ? Arow[k] : 0.f;
        }
        #pragma unroll
        for (int i = 0; i < 8; i++) {
            int k = k0 + wk + i;
            Bsf[wk + i][wslot] = (k < K) ? Wrow[k] : 0.f;
        }
        __syncthreads();
        #pragma unroll
        for (int k = 0; k < BK; k++) {
            float4 a0 = *(const float4*)&As[k][tm];
            float4 a1 = *(const float4*)&As[k][tm + 4];
            const unsigned long long* bp = (const unsigned long long*)&Bsf[k][0];
            unsigned long long b[4];
            b[0] = bp[tx]; b[1] = bp[tx + 16]; b[2] = bp[tx + 32]; b[3] = bp[tx + 48];
            unsigned long long ad[8];
            ad[0] = pack2(a0.x, a0.x); ad[1] = pack2(a0.y, a0.y);
            ad[2] = pack2(a0.z, a0.z); ad[3] = pack2(a0.w, a0.w);
            ad[4] = pack2(a1.x, a1.x); ad[5] = pack2(a1.y, a1.y);
            ad[6] = pack2(a1.z, a1.z); ad[7] = pack2(a1.w, a1.w);
            #pragma unroll
            for (int i = 0; i < 8; i++)
                #pragma unroll
                for (int j = 0; j < 4; j++)
                    ffma2(acc[i][j], ad[i], b[j]);
        }
        __syncthreads();
    }

    // epilogue: thread writes cols {tx+16r} and {tx+16r+64}, rows tm..tm+7
    float blo[4], bhi[4];
    #pragma unroll
    for (int j = 0; j < 4; j++) {
        blo[j] = bias[tx + 16*j];
        bhi[j] = bias[tx + 16*j + 64];
    }
    #pragma unroll
    for (int i = 0; i < 8; i++) {
        float* crow = C + (m0 + tm + i) * (long)HH;
        #pragma unroll
        for (int j = 0; j < 4; j++) {
            float2 v = unpack2(acc[i][j]);
            crow[tx + 16*j]      = v.x + blo[j];
            crow[tx + 16*j + 64] = v.y + bhi[j];
        }
    }
}

// -------- gather + relu (GIN self-term + neighbor sum + ReLU) --------
__global__ void __launch_bounds__(256) gather_relu_kernel(
    const float* __restrict__ Y, float* __restrict__ Out)
{
    int wid  = threadIdx.x >> 5, lane = threadIdx.x & 31;
    int dst  = blockIdx.x * 8 + wid;
    int t    = blockIdx.y;
    if (dst >= NN) return;
    const float* base = Y + t * NN * HH;
    float4 acc = *(const float4*)&base[dst * HH + lane * 4];
    int s   = g_start[t*NN + dst];
    int cnt = g_cnt  [t*NN + dst];
    const int* ep = g_eidx + t*EE + s;
    int i = 0;
    for (; i + 4 <= cnt; i += 4) {
        int s0 = ep[i], s1 = ep[i+1], s2 = ep[i+2], s3 = ep[i+3];
        float4 v0 = *(const float4*)&base[s0*HH + lane*4];
        float4 v1 = *(const float4*)&base[s1*HH + lane*4];
        float4 v2 = *(const float4*)&base[s2*HH + lane*4];
        float4 v3 = *(const float4*)&base[s3*HH + lane*4];
        acc.x += v0.x + v1.x + v2.x + v3.x;
        acc.y += v0.y + v1.y + v2.y + v3.y;
        acc.z += v0.z + v1.z + v2.z + v3.z;
        acc.w += v0.w + v1.w + v2.w + v3.w;
    }
    for (; i < cnt; i++) {
        int s0 = ep[i];
        float4 v = *(const float4*)&base[s0*HH + lane*4];
        acc.x += v.x; acc.y += v.y; acc.z += v.z; acc.w += v.w;
    }
    acc.x = fmaxf(acc.x, 0.f); acc.y = fmaxf(acc.y, 0.f);
    acc.z = fmaxf(acc.z, 0.f); acc.w = fmaxf(acc.w, 0.f);
    *(float4*)&Out[(t*NN + dst)*HH + lane*4] = acc;
}

// ---------------- mean pool over N ----------------
__global__ void pool_kernel(const float* __restrict__ Hin) {
    int t = blockIdx.x, c = threadIdx.x;   // 128 threads
    const float* p = Hin + t*NN*HH + c;
    float s0 = 0, s1 = 0, s2 = 0, s3 = 0;
    for (int n = 0; n < NN; n += 4) {
        s0 += p[(n+0)*HH];
        s1 += p[(n+1)*HH];
        s2 += p[(n+2)*HH];
        s3 += p[(n+3)*HH];
    }
    g_pool[t*HH + c] = (s0 + s1 + s2 + s3) * (1.f / NN);
}

// -------- input-side LSTM gates --------
__global__ void __launch_bounds__(512) gx_kernel(
    const int* __restrict__ dok, const float* __restrict__ emb,
    const float* __restrict__ w_ih, const float* __restrict__ b_ih,
    const float* __restrict__ b_hh)
{
    __shared__ float sseq[HH + DD];
    int t = blockIdx.x, j = threadIdx.x;
    if (j < HH)            sseq[j] = g_pool[t*HH + j];
    else if (j < HH + DD)  sseq[j] = emb[dok[t]*DD + (j - HH)];
    __syncthreads();
    const float* wr = w_ih + j * (HH + DD);
    float a0 = b_ih[j] + b_hh[j], a1 = 0.f;
    #pragma unroll
    for (int k = 0; k < HH + DD; k += 2) {
        a0 += wr[k]   * sseq[k];
        a1 += wr[k+1] * sseq[k+1];
    }
    g_Gx[t*G4 + j] = a0 + a1;
}

// ---------------- sequential LSTM + final FC ----------------
#define SPITCH 68
__global__ void __launch_bounds__(512) lstm_kernel(
    const float* __restrict__ w_hh, const float* __restrict__ w_fc,
    const float* __restrict__ b_fc, float* __restrict__ out)
{
    extern __shared__ float sm[];
    float* sW   = sm;                  // 512*68
    float* sh   = sW + G4*SPITCH;      // 128
    float* sg   = sh + HH;             // 512
    float* sred = sg + G4;             // 32

    int tid = threadIdx.x;

    float4 rw[16];
    const float4* wg4 = (const float4*)(w_hh + tid * HH);
    #pragma unroll
    for (int i = 0; i < 16; i++) rw[i] = wg4[i];          // cols 0..63

    for (int i = tid; i < G4 * 64; i += 512) {            // cols 64..127
        int r = i >> 6, c = i & 63;
        sW[r*SPITCH + c] = w_hh[r*HH + 64 + c];
    }
    if (tid < HH) sh[tid] = 0.f;
    float c_state = 0.f;
    float wfc = (tid < HH) ? w_fc[tid] : 0.f;
    float bfc = b_fc[0];
    __syncthreads();

    const float4* wr4 = (const float4*)(sW + tid * SPITCH);

    for (int t = 0; t < TT; t++) {
        const float4* sh4 = (const float4*)sh;
        float a0 = 0, a1 = 0, a2 = 0, a3 = 0;
        #pragma unroll
        for (int k = 0; k < 16; k++) {
            float4 hv = sh4[k]; float4 w = rw[k];
            a0 += w.x*hv.x; a1 += w.y*hv.y; a2 += w.z*hv.z; a3 += w.w*hv.w;
        }
        #pragma unroll
        for (int k = 0; k < 16; k++) {
            float4 hv = sh4[16 + k]; float4 w = wr4[k];
            a0 += w.x*hv.x; a1 += w.y*hv.y; a2 += w.z*hv.z; a3 += w.w*hv.w;
        }
        sg[tid] = g_Gx[t*G4 + tid] + (a0 + a1) + (a2 + a3);
        __syncthreads();
        if (tid < HH) {
            float ig = 1.f / (1.f + expf(-sg[tid]));
            float fg = 1.f / (1.f + expf(-sg[tid + HH]));
            float gg = tanhf(sg[tid + 2*HH]);
            float og = 1.f / (1.f + expf(-sg[tid + 3*HH]));
            c_state = fg * c_state + ig * gg;
            float h = og * tanhf(c_state);
            sh[tid] = h;
            float p = h * wfc;
            #pragma unroll
            for (int o = 16; o > 0; o >>= 1) p += __shfl_down_sync(0xffffffffu, p, o);
            if ((tid & 31) == 0) sred[tid >> 5] = p;
        }
        __syncthreads();
        if (tid == 0) out[t] = sred[0] + sred[1] + sred[2] + sred[3] + bfc;
    }
}

// ---------------- launch ----------------
extern "C" void kernel_launch(void* const* d_in, const int* in_sizes, int n_in,
                              void* d_out, int out_size)
{
    const float* x    = (const float*)d_in[0];
    const int*   ei   = (const int*)  d_in[1];
    const int*   dok  = (const int*)  d_in[2];
    const float* w1   = (const float*)d_in[3];
    const float* b1   = (const float*)d_in[4];
    const float* w2   = (const float*)d_in[5];
    const float* b2   = (const float*)d_in[6];
    const float* emb  = (const float*)d_in[7];
    const float* w_ih = (const float*)d_in[8];
    const float* w_hh = (const float*)d_in[9];
    const float* b_ih = (const float*)d_in[10];
    const float* b_hh = (const float*)d_in[11];
    const float* w_fc = (const float*)d_in[12];
    const float* b_fc = (const float*)d_in[13];
    float* out = (float*)d_out;

    float *pY, *pH1;
    cudaGetSymbolAddress((void**)&pY,  g_Y);
    cudaGetSymbolAddress((void**)&pH1, g_H1);

    // fused CSR build (shared by both GIN layers)
    csr_kernel<<<TT, 1024>>>(ei);

    // GIN layer 1: y = x@w1^T + b1 ; h1 = relu(y[dst] + sum y[src])
    gemm_bias_kernel<<<TT*NN/BM, 256>>>(x, w1, b1, pY, FF);
    dim3 gg((NN + 7)/8, TT);
    gather_relu_kernel<<<gg, 256>>>(pY, pH1);

    // GIN layer 2
    gemm_bias_kernel<<<TT*NN/BM, 256>>>(pH1, w2, b2, pY, HH);
    gather_relu_kernel<<<gg, 256>>>(pY, pH1);

    // pool, LSTM input gates, sequential LSTM + FC
    pool_kernel<<<TT, HH>>>(pH1);
    gx_kernel<<<TT, 512>>>(dok, emb, w_ih, b_ih, b_hh);

    size_t lsm = (size_t)(G4*SPITCH + HH + G4 + 32) * sizeof(float);
    cudaFuncSetAttribute(lstm_kernel, cudaFuncAttributeMaxDynamicSharedMemorySize, (int)lsm);
    lstm_kernel<<<1, 512, lsm>>>(w_hh, w_fc, b_fc, out);
}